// round 16
// baseline (speedup 1.0000x reference)
#include <cuda_runtime.h>
#include <stdint.h>
#include <math.h>

#define NH 8
#define TS 128
#define DH 64
#define DM 512

typedef unsigned long long u64;
typedef unsigned int u32;

// ---------------- scratch (static device memory; no allocations) ----------------
__device__ float g_part[10*131072];   // proj partials: [ksplit(2)][proj(5)][bn(16)][p(128)][h(64)]
__device__ float g_k1[2*NH*TS*DH];
__device__ float g_k2[2*NH*TS*DH];
__device__ float g_q [2*NH*TS*DH];
__device__ float g_va[2*NH*TS*DH];
__device__ float g_vb[2*NH*TS*DH];
__device__ float g_z [2*TS*NH*DH];    // TRANSPOSED: [b*128+p][n*64+h]  (256 x 512)
__device__ float g_opart[4*256*512];  // out partials: [ksplit(4)][row(256)][d(512)]

// packed fp32x2 ops (PTX-only; ptxas never auto-fuses)
__device__ __forceinline__ u64 fma2(u64 a, u64 b, u64 c) {
    u64 d;
    asm("fma.rn.f32x2 %0, %1, %2, %3;" : "=l"(d) : "l"(a), "l"(b), "l"(c));
    return d;
}
__device__ __forceinline__ u64 mul2(u64 a, u64 b) {
    u64 d;
    asm("mul.rn.f32x2 %0, %1, %2;" : "=l"(d) : "l"(a), "l"(b));
    return d;
}
// PURE shared loads (non-volatile, no clobber): lets ptxas batch/hoist/CSE them.
// Safe because all consumed smem is written before a __syncthreads() barrier and
// post-phase reads use plain C++ loads.
__device__ __forceinline__ void lds2(u64& a, u64& b, u32 addr) {
    asm("ld.shared.v2.u64 {%0, %1}, [%2];" : "=l"(a), "=l"(b) : "r"(addr));
}
__device__ __forceinline__ float2 unpack2(u64 v) {
    float2 f;
    asm("mov.b64 {%0, %1}, %2;" : "=f"(f.x), "=f"(f.y) : "l"(v));
    return f;
}

// Fast exp: scores are tiny (|x| << 1); Taylor deg-8 on |x|<=0.9 (rel err ~1e-6),
// exact expf fallback otherwise (never hit on real data; stale rows are zero-filled).
__device__ __forceinline__ float fast_exp(float x) {
    if (fabsf(x) > 0.9f) return expf(x);
    float r = 1.f/40320.f;
    r = r*x + 1.f/5040.f;
    r = r*x + 1.f/720.f;
    r = r*x + 1.f/120.f;
    r = r*x + 1.f/24.f;
    r = r*x + 1.f/6.f;
    r = r*x + 0.5f;
    r = r*x + 1.f;
    r = r*x + 1.f;
    return r;
}

// ---------------- kernel 1a: projections, K-split x2 -> partials ----------------
// grid (40, 8, 2): x = proj*8 + ptile*2 + kh. Block = [32p x 64h], K = 256. 128 threads.
__global__ void proj_kernel(const float* __restrict__ x,
                            const float* __restrict__ Wk1, const float* __restrict__ Wk2,
                            const float* __restrict__ Wq,  const float* __restrict__ Wv12)
{
    __shared__ __align__(16) float xs[32*33];
    __shared__ __align__(16) float ws[32*68];
    int tid = threadIdx.x;
    int px = blockIdx.x;
    int n  = blockIdx.y;
    int b  = blockIdx.z;
    int proj = px >> 3;
    int p0 = ((px >> 1) & 3) * 32;
    int kh = px & 1;
    int kbase = kh * 256;

    const float* W;
    if (proj == 0)      W = Wk1 + n*DM*DH;
    else if (proj == 1) W = Wk2 + n*DM*DH;
    else if (proj == 2) W = Wq  + n*DM*DH;
    else if (proj == 3) W = Wv12 + n*2*DM*DH;
    else                W = Wv12 + n*2*DM*DH + DM*DH;

    const float* xb = x + b*TS*DM;
    int ty = tid >> 4, tx = tid & 15;      // 8 x 16 threads -> 4p x 4h each
    float acc[4][4];
    #pragma unroll
    for (int p = 0; p < 4; p++)
        #pragma unroll
        for (int c = 0; c < 4; c++) acc[p][c] = 0.f;

    for (int k0 = kbase; k0 < kbase + 256; k0 += 32) {
        #pragma unroll
        for (int r = 0; r < 8; r++) {
            int e = tid + r*128;           // 1024: 32p x 32k
            int pp = e >> 5, kk = e & 31;
            xs[pp*33 + kk] = xb[(p0+pp)*DM + k0 + kk];
        }
        #pragma unroll
        for (int r = 0; r < 16; r++) {
            int e = tid + r*128;           // 2048: 32k x 64h
            int kk = e >> 6, hh = e & 63;
            ws[kk*68 + hh] = W[(k0+kk)*DH + hh];
        }
        __syncthreads();
        #pragma unroll
        for (int k = 0; k < 32; k++) {
            float4 bv = *(const float4*)&ws[k*68 + tx*4];
            #pragma unroll
            for (int p = 0; p < 4; p++) {
                float a = xs[(ty*4+p)*33 + k];
                acc[p][0] += a*bv.x; acc[p][1] += a*bv.y;
                acc[p][2] += a*bv.z; acc[p][3] += a*bv.w;
            }
        }
        __syncthreads();
    }
    int bn = b*NH + n;
    float* dst = g_part + (kh*5 + proj)*131072;
    #pragma unroll
    for (int p = 0; p < 4; p++) {
        int prow = p0 + ty*4 + p;
        float* o = dst + (bn*TS + prow)*DH + tx*4;
        #pragma unroll
        for (int c = 0; c < 4; c++) o[c] = acc[p][c];
    }
}

// ---------------- kernel 1b: reduce K-split partials + bias ----------------
// grid 640, 256 threads, one float4 each (163840 float4 total).
__global__ void proj_reduce(const float* __restrict__ bk1, const float* __restrict__ bk2,
                            const float* __restrict__ bq)
{
    int idx4 = blockIdx.x*256 + threadIdx.x;
    int e = idx4*4;
    int proj = e >> 17;                 // /131072
    int rem  = e & 131071;
    float4 a = *(const float4*)(g_part + proj*131072 + rem);
    float4 bpart = *(const float4*)(g_part + (5+proj)*131072 + rem);
    a.x += bpart.x; a.y += bpart.y; a.z += bpart.z; a.w += bpart.w;

    if (proj < 3) {
        int n = (rem >> 13) & 7;
        int h = rem & 63;
        const float* bias = (proj == 0) ? bk1 : (proj == 1) ? bk2 : bq;
        const float4 bv = *(const float4*)(bias + n*DH + h);
        a.x += bv.x; a.y += bv.y; a.z += bv.z; a.w += bv.w;
    }
    float* dst = (proj == 0) ? g_k1 : (proj == 1) ? g_k2 : (proj == 2) ? g_q
               : (proj == 3) ? g_va : g_vb;
    *(float4*)(dst + rem) = a;
}

// ---------------- kernel 2: FOUR queries per block: raw k1/k2, q folded at tile level ----------
// grid (32, 8, 2), 256 threads = 8 warps. Q = 4x..4x+3. Tiles 8x8 over (s,t), i<=j.
// Per tile lane (p,r): prod = k1[s]*k2[t] (f32x2); acc[q] += prod*q[q] (broadcast q from smem).
// z output written TRANSPOSED to g_z[(b*TS+Q)][n*DH+h].
#define MAXT 136
__global__ __launch_bounds__(256, 2) void attn_kernel(const float* __restrict__ bv12)
{
    extern __shared__ __align__(16) float sm[];
    float* sk1  = sm;                     // 128 x 68 (phase2: va)
    float* sk2  = sk1 + 128*68;           // 128 x 68 (phase2: vb)
    float* sp   = sk2 + 128*68;           // 4 x MAXT x 16 (per q: row[8], col[8])
    float* srA  = sp  + 4*MAXT*16;        // 4 x 128 row sums
    float* scB  = srA + 4*128;            // 4 x 128 col sums
    float* sq   = scB + 4*128;            // 4 x 64 q-vectors
    float* sden = sq  + 4*64;             // 4

    int tid = threadIdx.x;
    int wid = tid >> 5, lane = tid & 31;
    int p = lane >> 3, r = lane & 7;
    int n = blockIdx.y, b = blockIdx.z;
    int bn = b*NH + n;
    int Q0 = blockIdx.x*4;
    int QD = Q0 + 3;

    int T8 = (QD + 7) >> 3;
    int ntiles = T8*(T8+1)/2;

    // load 4 q-vectors
    const float4* gq4 = (const float4*)(g_q + (bn*TS + Q0)*DH);
    if (tid < 64) ((float4*)sq)[tid] = gq4[tid];   // [q][16 float4] contiguous

    const float4* gk14 = (const float4*)(g_k1 + bn*TS*DH);
    const float4* gk24 = (const float4*)(g_k2 + bn*TS*DH);
    float4* sk14 = (float4*)sk1;
    float4* sk24 = (float4*)sk2;
    u32 k1_b = (u32)__cvta_generic_to_shared(sk1);
    u32 k2_b = (u32)__cvta_generic_to_shared(sk2);
    u32 sq_b = (u32)__cvta_generic_to_shared(sq);

    int nload = QD * 16;                  // rows 0..QD-1
    for (int e = tid; e < nload; e += 256) {
        int s = e >> 4, h4 = e & 15;
        sk14[s*17 + h4] = gk14[e];
        sk24[s*17 + h4] = gk24[e];
    }
    // zero-fill stale rows [QD, 8*T8) so tile math stays on the fast exp path
    float4 zz = make_float4(0.f,0.f,0.f,0.f);
    for (int e = tid; e < (8*T8 - QD)*16; e += 256) {
        int s = QD + (e >> 4), h4 = e & 15;
        sk14[s*17 + h4] = zz;
        sk24[s*17 + h4] = zz;
    }
    __syncthreads();

    const float inv = 1.f/64.f;

    for (int tile = wid; tile < ntiles; tile += 8) {
        // decode tile -> (i, j), i <= j (warp-uniform)
        int j = (int)((sqrtf(8.f*(float)tile + 1.f) - 1.f) * 0.5f);
        while ((j+1)*(j+2)/2 <= tile) j++;
        while (j*(j+1)/2 > tile) j--;
        int i = tile - j*(j+1)/2;
        int s0 = i*8, t0 = j*8;

        u32 aA = k1_b + (s0 + p)*272;             // 17 float4 * 16B row stride
        u32 aB = aA + 4*272;
        u32 aK = k2_b + (t0 + r)*272;
        u64 acc[4][2][2];                          // [q][row][half]
        #pragma unroll
        for (int qq = 0; qq < 4; qq++)
            #pragma unroll
            for (int rr = 0; rr < 2; rr++) { acc[qq][rr][0] = 0ull; acc[qq][rr][1] = 0ull; }

        #pragma unroll
        for (int h4 = 0; h4 < 16; h4++) {
            u64 b0, b1, x0, x1, y0, y1;
            lds2(b0, b1, aK + h4*16);
            lds2(x0, x1, aA + h4*16);
            lds2(y0, y1, aB + h4*16);
            u64 p0a = mul2(x0, b0), p0b = mul2(x1, b1);   // row s0+p
            u64 p1a = mul2(y0, b0), p1b = mul2(y1, b1);   // row s0+p+4
            #pragma unroll
            for (int qq = 0; qq < 4; qq++) {
                u64 q0, q1;
                lds2(q0, q1, sq_b + qq*256 + h4*16);      // broadcast; CSE-able across tiles
                acc[qq][0][0] = fma2(p0a, q0, acc[qq][0][0]);
                acc[qq][0][1] = fma2(p0b, q1, acc[qq][0][1]);
                acc[qq][1][0] = fma2(p1a, q0, acc[qq][1][0]);
                acc[qq][1][1] = fma2(p1b, q1, acc[qq][1][1]);
            }
        }

        int sa = s0 + p, sb = sa + 4, t = t0 + r;
        #pragma unroll
        for (int qq = 0; qq < 4; qq++) {
            int Qc = Q0 + qq;
            float2 u0 = unpack2(acc[qq][0][0]), u1 = unpack2(acc[qq][0][1]);
            float a0 = (u0.x + u1.x) + (u0.y + u1.y);
            float2 v0 = unpack2(acc[qq][1][0]), v1 = unpack2(acc[qq][1][1]);
            float a1 = (v0.x + v1.x) + (v0.y + v1.y);

            float e0 = (sa < t && t < Qc) ? fast_exp(a0 * inv) : 0.f;
            float e1 = (sb < t && t < Qc) ? fast_exp(a1 * inv) : 0.f;

            float r0 = e0, r1 = e1;
            #pragma unroll
            for (int o = 4; o > 0; o >>= 1) {
                r0 += __shfl_down_sync(0xffffffffu, r0, o);
                r1 += __shfl_down_sync(0xffffffffu, r1, o);
            }
            float c = e0 + e1;
            c += __shfl_down_sync(0xffffffffu, c, 16);
            c += __shfl_down_sync(0xffffffffu, c, 8);

            float* pp = sp + qq*MAXT*16 + tile*16;
            if (r == 0) { pp[p] = r0; pp[p+4] = r1; }
            if (lane < 8) pp[8 + lane] = c;
        }
    }
    __syncthreads();

    // reload sk1/sk2 with va/vb (serves all four queries)
    {
        const float4* gva4 = (const float4*)(g_va + bn*TS*DH);
        const float4* gvb4 = (const float4*)(g_vb + bn*TS*DH);
        for (int e = tid; e < nload; e += 256) {
            int s = e >> 4, h4 = e & 15;
            sk14[s*17 + h4] = gva4[e];
            sk24[s*17 + h4] = gvb4[e];
        }
    }
    // deterministic row/col reductions for all four queries
    #pragma unroll
    for (int qq = 0; qq < 4; qq++) {
        const float* spq = sp + qq*MAXT*16;
        if (tid < 128) {
            int s = tid, i = s >> 3, pr = s & 7;
            float sum = 0.f;
            if (i < T8) {
                for (int j = i; j < T8; j++)
                    sum += spq[(j*(j+1)/2 + i)*16 + pr];
            }
            srA[qq*128 + s] = sum;
        } else {
            int t = tid - 128, j = t >> 3, rr = t & 7;
            float sum = 0.f;
            if (j < T8) {
                int base = (j*(j+1)/2)*16 + 8 + rr;
                for (int i2 = 0; i2 <= j; i2++) sum += spq[base + i2*16];
            }
            scB[qq*128 + t] = sum;
        }
    }
    __syncthreads();

    // denominators: warp w (0..3) reduces srA of query w
    if (tid < 128) {
        int qq = tid >> 5, l = tid & 31;
        const float* sr = srA + qq*128;
        float v = sr[l] + sr[l+32] + sr[l+64] + sr[l+96];
        #pragma unroll
        for (int o = 16; o > 0; o >>= 1) v += __shfl_down_sync(0xffffffffu, v, o);
        if (l == 0) sden[qq] = v;
    }

    // z sums: thread = (q, h); sum over s; write TRANSPOSED
    int zq = tid >> 6;                    // 0..3
    int zh = tid & 63;
    int Qz = Q0 + zq;
    float zacc = 0.f;
    {
        const float* sr = srA + zq*128;
        const float* sc = scB + zq*128;
        for (int s = 0; s < Qz; s++)
            zacc += sr[s]*sk1[s*68 + zh] + sc[s]*sk2[s*68 + zh];
    }
    __syncthreads();
    {
        float den = sden[zq];
        float outv = (Qz < 2) ? 0.f : zacc/den + bv12[n*DH + zh];
        g_z[(b*TS + Qz)*(NH*DH) + n*DH + zh] = outv;   // transposed layout
    }
}

// ---------------- kernel 3a: out partials = z[256 x 512] @ Wo[512 x 512], K-split x4 ----------
// grid (8, 16, 4): [32p x 32d] tile, K-chunk 128. 128 threads, thread = 2p x 4d.
__global__ void out_part_kernel(const float* __restrict__ Wo)
{
    __shared__ __align__(16) float zs[32*33];
    __shared__ __align__(16) float ws[32*36];
    int tid = threadIdx.x;
    int p0 = blockIdx.x * 32, d0 = blockIdx.y * 32;
    int ks = blockIdx.z;
    int ty = tid >> 3;              // 0..15 -> rows 2ty, 2ty+1
    int tx = tid & 7;               // 0..7  -> d = d0 + tx*4

    float acc[2][4];
    #pragma unroll
    for (int r = 0; r < 2; r++)
        #pragma unroll
        for (int c = 0; c < 4; c++) acc[r][c] = 0.f;

    for (int kc = 0; kc < 128; kc += 32) {
        int k0 = ks*128 + kc;
        #pragma unroll
        for (int r = 0; r < 8; r++) {
            int e = tid + r*128;            // 1024: 32p x 32k
            int pp = e >> 5, kk = e & 31;
            zs[pp*33 + kk] = g_z[(p0+pp)*512 + k0 + kk];
        }
        #pragma unroll
        for (int r = 0; r < 8; r++) {
            int e = tid + r*128;            // 1024: 32k x 32d
            int kk = e >> 5, dd = e & 31;
            ws[kk*36 + dd] = Wo[(k0+kk)*DM + d0 + dd];
        }
        __syncthreads();
        #pragma unroll
        for (int k = 0; k < 32; k++) {
            float4 w = *(const float4*)&ws[k*36 + tx*4];
            float a0 = zs[(ty*2)*33 + k];
            float a1 = zs[(ty*2+1)*33 + k];
            acc[0][0] += a0*w.x; acc[0][1] += a0*w.y; acc[0][2] += a0*w.z; acc[0][3] += a0*w.w;
            acc[1][0] += a1*w.x; acc[1][1] += a1*w.y; acc[1][2] += a1*w.z; acc[1][3] += a1*w.w;
        }
        __syncthreads();
    }
    float* dst = g_opart + ks*131072;
    #pragma unroll
    for (int r = 0; r < 2; r++) {
        int prow = p0 + ty*2 + r;
        float* o = dst + prow*512 + d0 + tx*4;
        #pragma unroll
        for (int c = 0; c < 4; c++) o[c] = acc[r][c];
    }
}

// ---------------- kernel 3b: reduce 4 out partials + bias ----------------
// grid 128, 256 threads, one float4 each (32768 float4).
__global__ void out_reduce(const float* __restrict__ bo, float* __restrict__ out)
{
    int idx4 = blockIdx.x*256 + threadIdx.x;
    int e = idx4*4;
    int d = e & 511;
    float4 a = *(const float4*)(g_opart + e);
    float4 b1 = *(const float4*)(g_opart + 131072 + e);
    float4 b2 = *(const float4*)(g_opart + 2*131072 + e);
    float4 b3 = *(const float4*)(g_opart + 3*131072 + e);
    float4 bv = *(const float4*)(bo + d);
    a.x = ((a.x + b1.x) + (b2.x + b3.x)) + bv.x;
    a.y = ((a.y + b1.y) + (b2.y + b3.y)) + bv.y;
    a.z = ((a.z + b1.z) + (b2.z + b3.z)) + bv.z;
    a.w = ((a.w + b1.w) + (b2.w + b3.w)) + bv.w;
    *(float4*)(out + e) = a;
}

// ---------------- launch ----------------
extern "C" void kernel_launch(void* const* d_in, const int* in_sizes, int n_in,
                              void* d_out, int out_size)
{
    const float* x    = (const float*)d_in[0];
    const float* Wk1  = (const float*)d_in[1];
    const float* Wk2  = (const float*)d_in[2];
    const float* Wq   = (const float*)d_in[3];
    const float* Wv12 = (const float*)d_in[4];
    const float* Wo   = (const float*)d_in[5];
    const float* bk1  = (const float*)d_in[6];
    const float* bk2  = (const float*)d_in[7];
    const float* bq   = (const float*)d_in[8];
    const float* bv12 = (const float*)d_in[9];
    const float* bo   = (const float*)d_in[10];
    float* out = (float*)d_out;

    proj_kernel<<<dim3(40, 8, 2), 128>>>(x, Wk1, Wk2, Wq, Wv12);
    proj_reduce<<<640, 256>>>(bk1, bk2, bq);

    int smem2 = (2*128*68 + 4*MAXT*16 + 4*128*2 + 4*64 + 4)*(int)sizeof(float);  // 109,584 B
    cudaFuncSetAttribute(attn_kernel, cudaFuncAttributeMaxDynamicSharedMemorySize, smem2);
    attn_kernel<<<dim3(32, 8, 2), 256, smem2>>>(bv12);

    out_part_kernel<<<dim3(8, 16, 4), 128>>>(Wo);
    out_reduce<<<128, 256>>>(bo, out);
}

// round 17
// speedup vs baseline: 1.6200x; 1.6200x over previous
#include <cuda_runtime.h>
#include <stdint.h>
#include <math.h>

#define NH 8
#define TS 128
#define DH 64
#define DM 512

typedef unsigned long long u64;
typedef unsigned int u32;

// ---------------- scratch (static device memory; no allocations) ----------------
__device__ float g_part[10*131072];   // proj partials: [ksplit(2)][proj(5)][bn(16)][p(128)][h(64)]
__device__ float g_k1[2*NH*TS*DH];
__device__ float g_k2[2*NH*TS*DH];
__device__ float g_q [2*NH*TS*DH];
__device__ float g_va[2*NH*TS*DH];
__device__ float g_vb[2*NH*TS*DH];
__device__ float g_z [2*TS*NH*DH];    // TRANSPOSED: [b*128+p][n*64+h]  (256 x 512)
__device__ float g_opart[8*256*512];  // out partials: [ksplit(8)][row(256)][d(512)]

// packed fp32x2 ops (PTX-only; ptxas never auto-fuses)
__device__ __forceinline__ u64 fma2(u64 a, u64 b, u64 c) {
    u64 d;
    asm("fma.rn.f32x2 %0, %1, %2, %3;" : "=l"(d) : "l"(a), "l"(b), "l"(c));
    return d;
}
__device__ __forceinline__ u64 mul2(u64 a, u64 b) {
    u64 d;
    asm("mul.rn.f32x2 %0, %1, %2;" : "=l"(d) : "l"(a), "l"(b));
    return d;
}
// volatile is load-bearing here: it acts as a scheduling fence that keeps ptxas
// from hoisting the whole unrolled tile's LDS into registers (R16 showed the
// non-volatile version spills and runs 1.6x slower).
__device__ __forceinline__ void lds2(u64& a, u64& b, u32 addr) {
    asm volatile("ld.shared.v2.u64 {%0, %1}, [%2];" : "=l"(a), "=l"(b) : "r"(addr));
}
__device__ __forceinline__ float2 unpack2(u64 v) {
    float2 f;
    asm("mov.b64 {%0, %1}, %2;" : "=f"(f.x), "=f"(f.y) : "l"(v));
    return f;
}

// Fast exp: scores are tiny (|x| << 1); Taylor deg-8 on |x|<=0.9 (rel err ~1e-6),
// exact expf fallback otherwise (never hit on real data; stale rows are zero-filled).
__device__ __forceinline__ float fast_exp(float x) {
    if (fabsf(x) > 0.9f) return expf(x);
    float r = 1.f/40320.f;
    r = r*x + 1.f/5040.f;
    r = r*x + 1.f/720.f;
    r = r*x + 1.f/120.f;
    r = r*x + 1.f/24.f;
    r = r*x + 1.f/6.f;
    r = r*x + 0.5f;
    r = r*x + 1.f;
    r = r*x + 1.f;
    return r;
}

// ---------------- kernel 1a: projections, K-split x2 -> partials ----------------
// grid (40, 8, 2): x = proj*8 + ptile*2 + kh. Block = [32p x 64h], K = 256. 128 threads.
__global__ void proj_kernel(const float* __restrict__ x,
                            const float* __restrict__ Wk1, const float* __restrict__ Wk2,
                            const float* __restrict__ Wq,  const float* __restrict__ Wv12)
{
    __shared__ __align__(16) float xs[32*33];
    __shared__ __align__(16) float ws[32*68];
    int tid = threadIdx.x;
    int px = blockIdx.x;
    int n  = blockIdx.y;
    int b  = blockIdx.z;
    int proj = px >> 3;
    int p0 = ((px >> 1) & 3) * 32;
    int kh = px & 1;
    int kbase = kh * 256;

    const float* W;
    if (proj == 0)      W = Wk1 + n*DM*DH;
    else if (proj == 1) W = Wk2 + n*DM*DH;
    else if (proj == 2) W = Wq  + n*DM*DH;
    else if (proj == 3) W = Wv12 + n*2*DM*DH;
    else                W = Wv12 + n*2*DM*DH + DM*DH;

    const float* xb = x + b*TS*DM;
    int ty = tid >> 4, tx = tid & 15;      // 8 x 16 threads -> 4p x 4h each
    float acc[4][4];
    #pragma unroll
    for (int p = 0; p < 4; p++)
        #pragma unroll
        for (int c = 0; c < 4; c++) acc[p][c] = 0.f;

    for (int k0 = kbase; k0 < kbase + 256; k0 += 32) {
        #pragma unroll
        for (int r = 0; r < 8; r++) {
            int e = tid + r*128;           // 1024: 32p x 32k
            int pp = e >> 5, kk = e & 31;
            xs[pp*33 + kk] = xb[(p0+pp)*DM + k0 + kk];
        }
        #pragma unroll
        for (int r = 0; r < 16; r++) {
            int e = tid + r*128;           // 2048: 32k x 64h
            int kk = e >> 6, hh = e & 63;
            ws[kk*68 + hh] = W[(k0+kk)*DH + hh];
        }
        __syncthreads();
        #pragma unroll
        for (int k = 0; k < 32; k++) {
            float4 bv = *(const float4*)&ws[k*68 + tx*4];
            #pragma unroll
            for (int p = 0; p < 4; p++) {
                float a = xs[(ty*4+p)*33 + k];
                acc[p][0] += a*bv.x; acc[p][1] += a*bv.y;
                acc[p][2] += a*bv.z; acc[p][3] += a*bv.w;
            }
        }
        __syncthreads();
    }
    int bn = b*NH + n;
    float* dst = g_part + (kh*5 + proj)*131072;
    #pragma unroll
    for (int p = 0; p < 4; p++) {
        int prow = p0 + ty*4 + p;
        float* o = dst + (bn*TS + prow)*DH + tx*4;
        #pragma unroll
        for (int c = 0; c < 4; c++) o[c] = acc[p][c];
    }
}

// ---------------- kernel 1b: reduce K-split partials + bias ----------------
// grid 640, 256 threads, one float4 each (163840 float4 total).
__global__ void proj_reduce(const float* __restrict__ bk1, const float* __restrict__ bk2,
                            const float* __restrict__ bq)
{
    int idx4 = blockIdx.x*256 + threadIdx.x;
    int e = idx4*4;
    int proj = e >> 17;                 // /131072
    int rem  = e & 131071;
    float4 a = *(const float4*)(g_part + proj*131072 + rem);
    float4 bpart = *(const float4*)(g_part + (5+proj)*131072 + rem);
    a.x += bpart.x; a.y += bpart.y; a.z += bpart.z; a.w += bpart.w;

    if (proj < 3) {
        int n = (rem >> 13) & 7;
        int h = rem & 63;
        const float* bias = (proj == 0) ? bk1 : (proj == 1) ? bk2 : bq;
        const float4 bv = *(const float4*)(bias + n*DH + h);
        a.x += bv.x; a.y += bv.y; a.z += bv.z; a.w += bv.w;
    }
    float* dst = (proj == 0) ? g_k1 : (proj == 1) ? g_k2 : (proj == 2) ? g_q
               : (proj == 3) ? g_va : g_vb;
    *(float4*)(dst + rem) = a;
}

// ---------------- kernel 2: FOUR queries per block: raw k1/k2, q folded at tile level ----------
// grid (32, 8, 2), 256 threads = 8 warps. Q = 4x..4x+3. Tiles 8x8 over (s,t), i<=j.
// Per tile lane (p,r): prod = k1[s]*k2[t] (f32x2); acc[q] += prod*q[q] (broadcast q from smem).
// z output written TRANSPOSED to g_z[(b*TS+Q)][n*DH+h].
#define MAXT 136
__global__ __launch_bounds__(256, 2) void attn_kernel(const float* __restrict__ bv12)
{
    extern __shared__ __align__(16) float sm[];
    float* sk1  = sm;                     // 128 x 68 (phase2: va)
    float* sk2  = sk1 + 128*68;           // 128 x 68 (phase2: vb)
    float* sp   = sk2 + 128*68;           // 4 x MAXT x 16 (per q: row[8], col[8])
    float* srA  = sp  + 4*MAXT*16;        // 4 x 128 row sums
    float* scB  = srA + 4*128;            // 4 x 128 col sums
    float* sq   = scB + 4*128;            // 4 x 64 q-vectors
    float* sden = sq  + 4*64;             // 4

    int tid = threadIdx.x;
    int wid = tid >> 5, lane = tid & 31;
    int p = lane >> 3, r = lane & 7;
    int n = blockIdx.y, b = blockIdx.z;
    int bn = b*NH + n;
    int Q0 = blockIdx.x*4;
    int QD = Q0 + 3;

    int T8 = (QD + 7) >> 3;
    int ntiles = T8*(T8+1)/2;

    // load 4 q-vectors
    const float4* gq4 = (const float4*)(g_q + (bn*TS + Q0)*DH);
    if (tid < 64) ((float4*)sq)[tid] = gq4[tid];   // [q][16 float4] contiguous

    const float4* gk14 = (const float4*)(g_k1 + bn*TS*DH);
    const float4* gk24 = (const float4*)(g_k2 + bn*TS*DH);
    float4* sk14 = (float4*)sk1;
    float4* sk24 = (float4*)sk2;
    u32 k1_b = (u32)__cvta_generic_to_shared(sk1);
    u32 k2_b = (u32)__cvta_generic_to_shared(sk2);
    u32 sq_b = (u32)__cvta_generic_to_shared(sq);

    int nload = QD * 16;                  // rows 0..QD-1
    for (int e = tid; e < nload; e += 256) {
        int s = e >> 4, h4 = e & 15;
        sk14[s*17 + h4] = gk14[e];
        sk24[s*17 + h4] = gk24[e];
    }
    // zero-fill stale rows [QD, 8*T8) so tile math stays on the fast exp path
    float4 zz = make_float4(0.f,0.f,0.f,0.f);
    for (int e = tid; e < (8*T8 - QD)*16; e += 256) {
        int s = QD + (e >> 4), h4 = e & 15;
        sk14[s*17 + h4] = zz;
        sk24[s*17 + h4] = zz;
    }
    __syncthreads();

    const float inv = 1.f/64.f;

    for (int tile = wid; tile < ntiles; tile += 8) {
        // decode tile -> (i, j), i <= j (warp-uniform)
        int j = (int)((sqrtf(8.f*(float)tile + 1.f) - 1.f) * 0.5f);
        while ((j+1)*(j+2)/2 <= tile) j++;
        while (j*(j+1)/2 > tile) j--;
        int i = tile - j*(j+1)/2;
        int s0 = i*8, t0 = j*8;

        u32 aA = k1_b + (s0 + p)*272;             // 17 float4 * 16B row stride
        u32 aB = aA + 4*272;
        u32 aK = k2_b + (t0 + r)*272;
        u64 acc[4][2][2];                          // [q][row][half]
        #pragma unroll
        for (int qq = 0; qq < 4; qq++)
            #pragma unroll
            for (int rr = 0; rr < 2; rr++) { acc[qq][rr][0] = 0ull; acc[qq][rr][1] = 0ull; }

        #pragma unroll
        for (int h4 = 0; h4 < 16; h4++) {
            u64 b0, b1, x0, x1, y0, y1;
            lds2(b0, b1, aK + h4*16);
            lds2(x0, x1, aA + h4*16);
            lds2(y0, y1, aB + h4*16);
            u64 p0a = mul2(x0, b0), p0b = mul2(x1, b1);   // row s0+p
            u64 p1a = mul2(y0, b0), p1b = mul2(y1, b1);   // row s0+p+4
            #pragma unroll
            for (int qq = 0; qq < 4; qq++) {
                u64 q0, q1;
                lds2(q0, q1, sq_b + qq*256 + h4*16);      // broadcast
                acc[qq][0][0] = fma2(p0a, q0, acc[qq][0][0]);
                acc[qq][0][1] = fma2(p0b, q1, acc[qq][0][1]);
                acc[qq][1][0] = fma2(p1a, q0, acc[qq][1][0]);
                acc[qq][1][1] = fma2(p1b, q1, acc[qq][1][1]);
            }
        }

        int sa = s0 + p, sb = sa + 4, t = t0 + r;
        #pragma unroll
        for (int qq = 0; qq < 4; qq++) {
            int Qc = Q0 + qq;
            float2 u0 = unpack2(acc[qq][0][0]), u1 = unpack2(acc[qq][0][1]);
            float a0 = (u0.x + u1.x) + (u0.y + u1.y);
            float2 v0 = unpack2(acc[qq][1][0]), v1 = unpack2(acc[qq][1][1]);
            float a1 = (v0.x + v1.x) + (v0.y + v1.y);

            float e0 = (sa < t && t < Qc) ? fast_exp(a0 * inv) : 0.f;
            float e1 = (sb < t && t < Qc) ? fast_exp(a1 * inv) : 0.f;

            float r0 = e0, r1 = e1;
            #pragma unroll
            for (int o = 4; o > 0; o >>= 1) {
                r0 += __shfl_down_sync(0xffffffffu, r0, o);
                r1 += __shfl_down_sync(0xffffffffu, r1, o);
            }
            float c = e0 + e1;
            c += __shfl_down_sync(0xffffffffu, c, 16);
            c += __shfl_down_sync(0xffffffffu, c, 8);

            float* pp = sp + qq*MAXT*16 + tile*16;
            if (r == 0) { pp[p] = r0; pp[p+4] = r1; }
            if (lane < 8) pp[8 + lane] = c;
        }
    }
    __syncthreads();

    // reload sk1/sk2 with va/vb (serves all four queries)
    {
        const float4* gva4 = (const float4*)(g_va + bn*TS*DH);
        const float4* gvb4 = (const float4*)(g_vb + bn*TS*DH);
        for (int e = tid; e < nload; e += 256) {
            int s = e >> 4, h4 = e & 15;
            sk14[s*17 + h4] = gva4[e];
            sk24[s*17 + h4] = gvb4[e];
        }
    }
    // deterministic row/col reductions for all four queries
    #pragma unroll
    for (int qq = 0; qq < 4; qq++) {
        const float* spq = sp + qq*MAXT*16;
        if (tid < 128) {
            int s = tid, i = s >> 3, pr = s & 7;
            float sum = 0.f;
            if (i < T8) {
                for (int j = i; j < T8; j++)
                    sum += spq[(j*(j+1)/2 + i)*16 + pr];
            }
            srA[qq*128 + s] = sum;
        } else {
            int t = tid - 128, j = t >> 3, rr = t & 7;
            float sum = 0.f;
            if (j < T8) {
                int base = (j*(j+1)/2)*16 + 8 + rr;
                for (int i2 = 0; i2 <= j; i2++) sum += spq[base + i2*16];
            }
            scB[qq*128 + t] = sum;
        }
    }
    __syncthreads();

    // denominators: warp w (0..3) reduces srA of query w
    if (tid < 128) {
        int qq = tid >> 5, l = tid & 31;
        const float* sr = srA + qq*128;
        float v = sr[l] + sr[l+32] + sr[l+64] + sr[l+96];
        #pragma unroll
        for (int o = 16; o > 0; o >>= 1) v += __shfl_down_sync(0xffffffffu, v, o);
        if (l == 0) sden[qq] = v;
    }

    // z sums: thread = (q, h); sum over s; write TRANSPOSED
    int zq = tid >> 6;                    // 0..3
    int zh = tid & 63;
    int Qz = Q0 + zq;
    float zacc = 0.f;
    {
        const float* sr = srA + zq*128;
        const float* sc = scB + zq*128;
        for (int s = 0; s < Qz; s++)
            zacc += sr[s]*sk1[s*68 + zh] + sc[s]*sk2[s*68 + zh];
    }
    __syncthreads();
    {
        float den = sden[zq];
        float outv = (Qz < 2) ? 0.f : zacc/den + bv12[n*DH + zh];
        g_z[(b*TS + Qz)*(NH*DH) + n*DH + zh] = outv;   // transposed layout
    }
}

// ---------------- kernel 3a: out partials = z[256 x 512] @ Wo[512 x 512], K-split x8 ----------
// grid (8, 16, 8): [32p x 32d] tile, K-chunk 64. 128 threads, thread = 2p x 4d.
__global__ void out_part_kernel(const float* __restrict__ Wo)
{
    __shared__ __align__(16) float zs[32*33];
    __shared__ __align__(16) float ws[32*36];
    int tid = threadIdx.x;
    int p0 = blockIdx.x * 32, d0 = blockIdx.y * 32;
    int ks = blockIdx.z;
    int ty = tid >> 3;              // 0..15 -> rows 2ty, 2ty+1
    int tx = tid & 7;               // 0..7  -> d = d0 + tx*4

    float acc[2][4];
    #pragma unroll
    for (int r = 0; r < 2; r++)
        #pragma unroll
        for (int c = 0; c < 4; c++) acc[r][c] = 0.f;

    #pragma unroll
    for (int kc = 0; kc < 64; kc += 32) {
        int k0 = ks*64 + kc;
        #pragma unroll
        for (int r = 0; r < 8; r++) {
            int e = tid + r*128;            // 1024: 32p x 32k
            int pp = e >> 5, kk = e & 31;
            zs[pp*33 + kk] = g_z[(p0+pp)*512 + k0 + kk];
        }
        #pragma unroll
        for (int r = 0; r < 8; r++) {
            int e = tid + r*128;            // 1024: 32k x 32d
            int kk = e >> 5, dd = e & 31;
            ws[kk*36 + dd] = Wo[(k0+kk)*DM + d0 + dd];
        }
        __syncthreads();
        #pragma unroll
        for (int k = 0; k < 32; k++) {
            float4 w = *(const float4*)&ws[k*36 + tx*4];
            float a0 = zs[(ty*2)*33 + k];
            float a1 = zs[(ty*2+1)*33 + k];
            acc[0][0] += a0*w.x; acc[0][1] += a0*w.y; acc[0][2] += a0*w.z; acc[0][3] += a0*w.w;
            acc[1][0] += a1*w.x; acc[1][1] += a1*w.y; acc[1][2] += a1*w.z; acc[1][3] += a1*w.w;
        }
        __syncthreads();
    }
    float* dst = g_opart + ks*131072;
    #pragma unroll
    for (int r = 0; r < 2; r++) {
        int prow = p0 + ty*2 + r;
        float* o = dst + prow*512 + d0 + tx*4;
        #pragma unroll
        for (int c = 0; c < 4; c++) o[c] = acc[r][c];
    }
}

// ---------------- kernel 3b: reduce 8 out partials + bias ----------------
// grid 128, 256 threads, one float4 each (32768 float4).
__global__ void out_reduce(const float* __restrict__ bo, float* __restrict__ out)
{
    int idx4 = blockIdx.x*256 + threadIdx.x;
    int e = idx4*4;
    int d = e & 511;
    float4 a0 = *(const float4*)(g_opart + e);
    float4 a1 = *(const float4*)(g_opart + 1*131072 + e);
    float4 a2 = *(const float4*)(g_opart + 2*131072 + e);
    float4 a3 = *(const float4*)(g_opart + 3*131072 + e);
    float4 a4 = *(const float4*)(g_opart + 4*131072 + e);
    float4 a5 = *(const float4*)(g_opart + 5*131072 + e);
    float4 a6 = *(const float4*)(g_opart + 6*131072 + e);
    float4 a7 = *(const float4*)(g_opart + 7*131072 + e);
    float4 bv = *(const float4*)(bo + d);
    float4 o;
    o.x = (((a0.x + a1.x) + (a2.x + a3.x)) + ((a4.x + a5.x) + (a6.x + a7.x))) + bv.x;
    o.y = (((a0.y + a1.y) + (a2.y + a3.y)) + ((a4.y + a5.y) + (a6.y + a7.y))) + bv.y;
    o.z = (((a0.z + a1.z) + (a2.z + a3.z)) + ((a4.z + a5.z) + (a6.z + a7.z))) + bv.z;
    o.w = (((a0.w + a1.w) + (a2.w + a3.w)) + ((a4.w + a5.w) + (a6.w + a7.w))) + bv.w;
    *(float4*)(out + e) = o;
}

// ---------------- launch ----------------
extern "C" void kernel_launch(void* const* d_in, const int* in_sizes, int n_in,
                              void* d_out, int out_size)
{
    const float* x    = (const float*)d_in[0];
    const float* Wk1  = (const float*)d_in[1];
    const float* Wk2  = (const float*)d_in[2];
    const float* Wq   = (const float*)d_in[3];
    const float* Wv12 = (const float*)d_in[4];
    const float* Wo   = (const float*)d_in[5];
    const float* bk1  = (const float*)d_in[6];
    const float* bk2  = (const float*)d_in[7];
    const float* bq   = (const float*)d_in[8];
    const float* bv12 = (const float*)d_in[9];
    const float* bo   = (const float*)d_in[10];
    float* out = (float*)d_out;

    proj_kernel<<<dim3(40, 8, 2), 128>>>(x, Wk1, Wk2, Wq, Wv12);
    proj_reduce<<<640, 256>>>(bk1, bk2, bq);

    int smem2 = (2*128*68 + 4*MAXT*16 + 4*128*2 + 4*64 + 4)*(int)sizeof(float);  // 109,584 B
    cudaFuncSetAttribute(attn_kernel, cudaFuncAttributeMaxDynamicSharedMemorySize, smem2);
    attn_kernel<<<dim3(32, 8, 2), 256, smem2>>>(bv12);

    out_part_kernel<<<dim3(8, 16, 8), 128>>>(Wo);
    out_reduce<<<128, 256>>>(bo, out);
}